// round 3
// baseline (speedup 1.0000x reference)
#include <cuda_runtime.h>
#include <cstdint>

// Problem shape (fixed by the dataset)
#define BSZ 32
#define TLEN 4096
#define CDIM 256
#define NPB (TLEN * CDIM)        // 1048576 elements per batch
#define NBINS 4096               // 12-bit bucket: (bits of fabs(x)) >> 19
#define CAP 131072               // candidate buffer capacity per batch
#define PAD 64                   // 64 uints = 256B stride -> distinct L2 lines

// ---------------- device scratch (static, allocation-free) ----------------
__device__ float    g_distrust[BSZ][PAD];
__device__ unsigned g_hist[BSZ][NBINS];
__device__ unsigned g_count[BSZ][PAD];
__device__ unsigned g_below[BSZ][PAD];
__device__ unsigned g_tick1[BSZ][PAD];
__device__ unsigned g_tick3[BSZ][PAD];
__device__ unsigned g_lo_bits[BSZ];
__device__ unsigned g_hi_bits[BSZ];
__device__ unsigned g_k0[BSZ];
__device__ unsigned g_k1[BSZ];
__device__ float    g_frac[BSZ];
__device__ float    g_thresh[BSZ];
__device__ unsigned g_buf[BSZ][CAP];

// ---------------- K0: zero scratch (graph replays need this) ----------------
__global__ void k0_zero() {
    unsigned i = blockIdx.x * blockDim.x + threadIdx.x;
    unsigned n = BSZ * NBINS;
    unsigned stride = gridDim.x * blockDim.x;
    unsigned* h = &g_hist[0][0];
    for (unsigned j = i; j < n; j += stride) h[j] = 0u;
    if (i < BSZ) {
        g_distrust[i][0] = 0.f;
        g_count[i][0] = 0u;
        g_below[i][0] = 0u;
        g_tick1[i][0] = 0u;
        g_tick3[i][0] = 0u;
    }
}

// ---------------- K2 logic (device fn, run by last K1 block of a batch) -----
__device__ void k2_buckets_dev(int b) {
    const int tid = threadIdx.x;
    __shared__ unsigned seg[256];
    __shared__ int sh_lob, sh_hib;
    __shared__ unsigned sh_rs0, sh_rs1;

    if (tid == 0) { sh_lob = NBINS; sh_hib = NBINS; }

    unsigned local[16];
    unsigned ssum = 0;
#pragma unroll
    for (int j = 0; j < 16; ++j) {
        local[j] = g_hist[b][tid * 16 + j];
        ssum += local[j];
    }
    seg[tid] = ssum;
    __syncthreads();

    if (tid == 0) {
        unsigned run = 0;
        for (int i = 0; i < 256; ++i) { unsigned v = seg[i]; seg[i] = run; run += v; }

        float db = g_distrust[b][0] * (1.f / TLEN);
        float p = 0.99f - 0.09f * db;
        double pos = (double)p * (double)(NPB - 1);
        unsigned k0 = (unsigned)pos;
        if (k0 > NPB - 1) k0 = NPB - 1;
        double frac = pos - (double)k0;
        unsigned k1 = (k0 + 1 <= NPB - 1) ? k0 + 1 : NPB - 1;
        g_k0[b] = k0;
        g_k1[b] = k1;
        g_frac[b] = (float)frac;

        const unsigned S = TLEN * 8;                // samples per batch
        double scale = (double)S / (double)NPB;
        long rs0 = (long)((double)k0 * scale) - 400;   // ~7 sigma margin
        long rs1 = (long)((double)k1 * scale) + 400;
        if (rs0 < 0) rs0 = 0;
        if (rs1 > (long)S - 1) rs1 = (long)S - 1;
        sh_rs0 = (unsigned)rs0;
        sh_rs1 = (unsigned)rs1;
    }
    __syncthreads();

    const unsigned rs0 = sh_rs0, rs1 = sh_rs1;
    unsigned cum = seg[tid];
    int lob = NBINS, hib = NBINS;
#pragma unroll
    for (int j = 0; j < 16; ++j) {
        cum += local[j];
        if (lob == NBINS && cum > rs0) lob = tid * 16 + j;
        if (hib == NBINS && cum > rs1) hib = tid * 16 + j;
    }
    if (lob < NBINS) atomicMin(&sh_lob, lob);
    if (hib < NBINS) atomicMin(&sh_hib, hib);
    __syncthreads();

    if (tid == 0) {
        int lo = (sh_lob < NBINS) ? sh_lob : NBINS - 1;
        int hi = (sh_hib < NBINS) ? sh_hib : NBINS - 1;
        g_lo_bits[b] = ((unsigned)lo) << 19;
        g_hi_bits[b] = ((unsigned)(hi + 1)) << 19;   // exclusive upper bound
        __threadfence();
    }
}

// ---------------- K1: distrust stats + subsampled histogram (+K2 tail) ------
// Grid: 1024 blocks x 256 threads. Block handles 128 rows (one batch each).
__global__ void __launch_bounds__(256) k1_stats(
    const float* __restrict__ s, const float* __restrict__ t,
    const float* __restrict__ risk)
{
    __shared__ unsigned sh_hist[NBINS];
    __shared__ float sh_wsum[8];
    __shared__ int sh_last;
    const int tid  = threadIdx.x;
    const int warp = tid >> 5;
    const int lane = tid & 31;

    for (int i = tid; i < NBINS; i += 256) sh_hist[i] = 0u;
    __syncthreads();

    const int row0 = blockIdx.x * 128;
    const int b = row0 / TLEN;
    const float rc = risk[b];

    float acc = 0.f;
#pragma unroll 4
    for (int it = 0; it < 16; ++it) {
        const int row = row0 + warp * 16 + it;
        const size_t base = (size_t)row * CDIM + lane * 8;
        float4 s0 = *(const float4*)(s + base);
        float4 s1 = *(const float4*)(s + base + 4);
        float4 t0 = *(const float4*)(t + base);
        float4 t1 = *(const float4*)(t + base + 4);

        // subsample: 8 of 256 elements per row -> 1/32 rate, 32768/batch
        if ((lane & 3) == 0) {
            unsigned bits = __float_as_uint(fabsf(s0.x));
            atomicAdd(&sh_hist[bits >> 19], 1u);
        }

        float d0 = s0.x - t0.x, d1 = s0.y - t0.y, d2 = s0.z - t0.z, d3 = s0.w - t0.w;
        float d4 = s1.x - t1.x, d5 = s1.y - t1.y, d6 = s1.z - t1.z, d7 = s1.w - t1.w;
        float r = d0*d0 + d1*d1 + d2*d2 + d3*d3 + d4*d4 + d5*d5 + d6*d6 + d7*d7;
#pragma unroll
        for (int o = 16; o; o >>= 1) r += __shfl_xor_sync(0xffffffffu, r, o);
        if (lane == 0) {
            float delta = r * (1.f / CDIM);
            float u = fminf(fmaxf(delta * 2.f, 0.f), 1.f);
            acc += fmaxf(u, rc * u);
        }
    }
    if (lane == 0) sh_wsum[warp] = acc;
    __syncthreads();
    if (tid == 0) {
        float ssum = 0.f;
        for (int w = 0; w < 8; ++w) ssum += sh_wsum[w];
        atomicAdd(&g_distrust[b][0], ssum);
    }
    for (int i = tid; i < NBINS; i += 256) {
        unsigned v = sh_hist[i];
        if (v) atomicAdd(&g_hist[b][i], v);
    }

    // last-block-done ticket -> run K2 for this batch inline
    __threadfence();
    __syncthreads();
    if (tid == 0) {
        unsigned done = atomicAdd(&g_tick1[b][0], 1u);
        sh_last = (done == 31u);                    // 32 blocks per batch
    }
    __syncthreads();
    if (sh_last) k2_buckets_dev(b);
}

// ---------------- K4 logic (device fn, run by last K3 block of a batch) -----
__device__ unsigned block_select(const unsigned* buf, unsigned m, unsigned r,
                                 unsigned* sh_hist) {
    __shared__ unsigned sh_byte, sh_r;
    unsigned prefix = 0, known = 0;
    for (int shift = 24; shift >= 0; shift -= 8) {
        for (int i = threadIdx.x; i < 256; i += blockDim.x) sh_hist[i] = 0u;
        __syncthreads();
        for (unsigned i = threadIdx.x; i < m; i += blockDim.x) {
            unsigned v = __ldcg(buf + i);
            if ((v & known) == prefix)
                atomicAdd(&sh_hist[(v >> shift) & 255u], 1u);
        }
        __syncthreads();
        if (threadIdx.x == 0) {
            unsigned cum = 0, byte = 255, rr = r;
            for (unsigned bb = 0; bb < 256; ++bb) {
                unsigned c = sh_hist[bb];
                if (cum + c > r) { byte = bb; rr = r - cum; break; }
                cum += c;
            }
            sh_byte = byte;
            sh_r = rr;
        }
        __syncthreads();
        prefix |= sh_byte << shift;
        known  |= 0xFFu << shift;
        r = sh_r;
        __syncthreads();
    }
    return prefix;
}

__device__ void k4_select_dev(int b, unsigned* sh_hist) {
    unsigned m = __ldcg(&g_count[b][0]);
    if (m > CAP) m = CAP;
    if (m == 0) { if (threadIdx.x == 0) g_thresh[b] = 0.f; return; }
    const long below = (long)__ldcg(&g_below[b][0]);
    long r0 = (long)g_k0[b] - below;
    long r1 = (long)g_k1[b] - below;
    if (r0 < 0) r0 = 0;
    if (r1 < 0) r1 = 0;
    if (r0 >= (long)m) r0 = m - 1;
    if (r1 >= (long)m) r1 = m - 1;
    unsigned v0 = block_select(g_buf[b], m, (unsigned)r0, sh_hist);
    unsigned v1 = block_select(g_buf[b], m, (unsigned)r1, sh_hist);
    if (threadIdx.x == 0) {
        float f0 = __uint_as_float(v0);
        float f1 = __uint_as_float(v1);
        g_thresh[b] = f0 + (f1 - f0) * g_frac[b];
        __threadfence();
    }
}

// ---------------- K3: exact below-count + compaction (+K4 tail) -------------
// One block = one contiguous 8192-element chunk of ONE batch; 4096 blocks.
// Candidates are rare (~3-5%): predicated per-candidate smem slot reserve,
// then ONE global atomic per block reserves the output range.
__global__ void __launch_bounds__(256) k3_compact(const float* __restrict__ s) {
    __shared__ unsigned sh_buf[8192];
    __shared__ unsigned sh_cnt, sh_base;
    __shared__ int sh_below[8];
    __shared__ int sh_last;

    const int tid  = threadIdx.x;
    const int warp = tid >> 5;
    const int lane = tid & 31;
    const int b     = blockIdx.x >> 7;       // 128 blocks per batch
    const int chunk = blockIdx.x & 127;

    if (tid == 0) sh_cnt = 0;
    __syncthreads();

    const unsigned lo = g_lo_bits[b];
    const unsigned hi = g_hi_bits[b];
    const float4* s4 = (const float4*)s + (size_t)b * (NPB / 4) + (size_t)chunk * 2048;

    int below = 0;
#pragma unroll
    for (int it = 0; it < 8; ++it) {
        float4 v = s4[it * 256 + tid];
        unsigned bv[4];
        bv[0] = __float_as_uint(fabsf(v.x));
        bv[1] = __float_as_uint(fabsf(v.y));
        bv[2] = __float_as_uint(fabsf(v.z));
        bv[3] = __float_as_uint(fabsf(v.w));
#pragma unroll
        for (int j = 0; j < 4; ++j) {
            below += (bv[j] < lo);
            if (bv[j] >= lo && bv[j] < hi) {
                unsigned slot = atomicAdd(&sh_cnt, 1u);
                sh_buf[slot] = bv[j];
            }
        }
    }

    // block-reduce below-count -> single global atomic
#pragma unroll
    for (int o = 16; o; o >>= 1) below += __shfl_xor_sync(0xffffffffu, below, o);
    if (lane == 0) sh_below[warp] = below;
    __syncthreads();
    if (tid == 0) {
        int tot = 0;
        for (int w = 0; w < 8; ++w) tot += sh_below[w];
        if (tot) atomicAdd(&g_below[b][0], (unsigned)tot);
        sh_base = atomicAdd(&g_count[b][0], sh_cnt);
    }
    __syncthreads();

    // coalesced copy-out of staged candidates
    const unsigned cnt = sh_cnt, gbase = sh_base;
    for (unsigned i = tid; i < cnt; i += 256) {
        unsigned off = gbase + i;
        if (off < CAP) g_buf[b][off] = sh_buf[i];
    }

    // last-block-done ticket -> run K4 for this batch inline
    __threadfence();
    __syncthreads();
    if (tid == 0) {
        unsigned done = atomicAdd(&g_tick3[b][0], 1u);
        sh_last = (done == 127u);                   // 128 blocks per batch
    }
    __syncthreads();
    if (sh_last) k4_select_dev(b, sh_buf);          // reuse smem as hist
}

// ---------------- K5: clip stream -------------------------------------------
__global__ void __launch_bounds__(256) k5_clip(const float* __restrict__ s,
                                               float* __restrict__ out)
{
    const float4* s4 = (const float4*)s;
    float4* o4 = (float4*)out;
    const unsigned total4 = (unsigned)BSZ * (NPB / 4);
    const unsigned stride = gridDim.x * blockDim.x;
    for (unsigned i = blockIdx.x * blockDim.x + threadIdx.x; i < total4; i += stride) {
        const int b = i >> 18;
        const float th = g_thresh[b];
        float4 v = __ldcs(s4 + i);
        v.x = fminf(fmaxf(v.x, -th), th);
        v.y = fminf(fmaxf(v.y, -th), th);
        v.z = fminf(fmaxf(v.z, -th), th);
        v.w = fminf(fmaxf(v.w, -th), th);
        __stcs(o4 + i, v);
    }
}

// ---------------- launch -----------------------------------------------------
extern "C" void kernel_launch(void* const* d_in, const int* in_sizes, int n_in,
                              void* d_out, int out_size)
{
    const float* s    = (const float*)d_in[0];
    const float* t    = (const float*)d_in[1];
    const float* risk = (const float*)d_in[2];
    float* out = (float*)d_out;

    k0_zero<<<512, 256>>>();
    k1_stats<<<1024, 256>>>(s, t, risk);
    k3_compact<<<4096, 256>>>(s);
    k5_clip<<<8192, 256>>>(s, out);
}

// round 4
// speedup vs baseline: 1.2540x; 1.2540x over previous
#include <cuda_runtime.h>
#include <cstdint>

// Problem shape (fixed by the dataset)
#define BSZ 32
#define TLEN 4096
#define CDIM 256
#define NPB (TLEN * CDIM)        // 1048576 elements per batch
#define NBINS 4096               // coarse: (bits of fabs(x)) >> 19
#define FINEBINS 4096            // fine hist over candidate window
#define CAP 131072               // candidate buffer capacity per batch
#define PAD 64                   // 256B stride -> distinct L2 lines
#define STASH 16                 // per-thread candidate stash (spill path for more)
#define LIST_CAP 4096            // K4 per-bin collection capacity

// ---------------- device scratch (static, allocation-free) ----------------
__device__ float    g_distrust[BSZ][PAD];
__device__ unsigned g_hist[BSZ][NBINS];
__device__ unsigned g_fine[BSZ][FINEBINS];
__device__ unsigned g_count[BSZ][PAD];
__device__ unsigned g_below[BSZ][PAD];
__device__ unsigned g_lo_bits[BSZ];
__device__ unsigned g_hi_bits[BSZ];
__device__ unsigned g_shift[BSZ];
__device__ unsigned g_k0[BSZ];
__device__ unsigned g_k1[BSZ];
__device__ float    g_frac[BSZ];
__device__ float    g_thresh[BSZ];
__device__ unsigned g_buf[BSZ][CAP];

// ---------------- K0: zero scratch (graph replays need this) ----------------
__global__ void k0_zero() {
    unsigned i = blockIdx.x * blockDim.x + threadIdx.x;
    unsigned stride = gridDim.x * blockDim.x;
    unsigned n1 = BSZ * NBINS;
    unsigned* h = &g_hist[0][0];
    for (unsigned j = i; j < n1; j += stride) h[j] = 0u;
    unsigned n2 = BSZ * FINEBINS;
    unsigned* f = &g_fine[0][0];
    for (unsigned j = i; j < n2; j += stride) f[j] = 0u;
    if (i < BSZ) {
        g_distrust[i][0] = 0.f;
        g_count[i][0] = 0u;
        g_below[i][0] = 0u;
    }
}

// ---------------- K1: distrust stats + subsampled histogram ----------------
// Grid: 1024 blocks x 256 threads. Block handles 128 rows (one batch each).
__global__ void __launch_bounds__(256) k1_stats(
    const float* __restrict__ s, const float* __restrict__ t,
    const float* __restrict__ risk)
{
    __shared__ unsigned sh_hist[NBINS];
    __shared__ float sh_wsum[8];
    const int tid  = threadIdx.x;
    const int warp = tid >> 5;
    const int lane = tid & 31;

    for (int i = tid; i < NBINS; i += 256) sh_hist[i] = 0u;
    __syncthreads();

    const int row0 = blockIdx.x * 128;
    const int b = row0 / TLEN;
    const float rc = risk[b];

    float acc = 0.f;
#pragma unroll 4
    for (int it = 0; it < 16; ++it) {
        const int row = row0 + warp * 16 + it;
        const size_t base = (size_t)row * CDIM + lane * 8;
        float4 s0 = *(const float4*)(s + base);
        float4 s1 = *(const float4*)(s + base + 4);
        float4 t0 = __ldcs((const float4*)(t + base));
        float4 t1 = __ldcs((const float4*)(t + base + 4));

        // subsample: 8 of 256 elements per row -> 1/32 rate, 32768/batch
        if ((lane & 3) == 0) {
            unsigned bits = __float_as_uint(fabsf(s0.x));
            atomicAdd(&sh_hist[bits >> 19], 1u);
        }

        float d0 = s0.x - t0.x, d1 = s0.y - t0.y, d2 = s0.z - t0.z, d3 = s0.w - t0.w;
        float d4 = s1.x - t1.x, d5 = s1.y - t1.y, d6 = s1.z - t1.z, d7 = s1.w - t1.w;
        float r = d0*d0 + d1*d1 + d2*d2 + d3*d3 + d4*d4 + d5*d5 + d6*d6 + d7*d7;
#pragma unroll
        for (int o = 16; o; o >>= 1) r += __shfl_xor_sync(0xffffffffu, r, o);
        if (lane == 0) {
            float delta = r * (1.f / CDIM);
            float u = fminf(fmaxf(delta * 2.f, 0.f), 1.f);
            acc += fmaxf(u, rc * u);
        }
    }
    if (lane == 0) sh_wsum[warp] = acc;
    __syncthreads();
    if (tid == 0) {
        float ssum = 0.f;
        for (int w = 0; w < 8; ++w) ssum += sh_wsum[w];
        atomicAdd(&g_distrust[b][0], ssum);
    }
    for (int i = tid; i < NBINS; i += 256) {
        unsigned v = sh_hist[i];
        if (v) atomicAdd(&g_hist[b][i], v);
    }
}

// ---------------- K2: ranks + candidate window + fine shift -----------------
// 32 blocks (one per batch) x 256 threads.
__global__ void __launch_bounds__(256) k2_buckets() {
    const int b = blockIdx.x;
    const int tid = threadIdx.x;
    __shared__ unsigned seg[256];
    __shared__ int sh_lob, sh_hib;
    __shared__ unsigned sh_rs0, sh_rs1;

    if (tid == 0) { sh_lob = NBINS; sh_hib = NBINS; }

    unsigned local[16];
    unsigned ssum = 0;
#pragma unroll
    for (int j = 0; j < 16; ++j) {
        local[j] = g_hist[b][tid * 16 + j];
        ssum += local[j];
    }
    seg[tid] = ssum;
    __syncthreads();

    if (tid == 0) {
        unsigned run = 0;
        for (int i = 0; i < 256; ++i) { unsigned v = seg[i]; seg[i] = run; run += v; }

        float db = g_distrust[b][0] * (1.f / TLEN);
        float p = 0.99f - 0.09f * db;
        double pos = (double)p * (double)(NPB - 1);
        unsigned k0 = (unsigned)pos;
        if (k0 > NPB - 1) k0 = NPB - 1;
        double frac = pos - (double)k0;
        unsigned k1 = (k0 + 1 <= NPB - 1) ? k0 + 1 : NPB - 1;
        g_k0[b] = k0;
        g_k1[b] = k1;
        g_frac[b] = (float)frac;

        const unsigned S = TLEN * 8;                // samples per batch
        double scale = (double)S / (double)NPB;
        long rs0 = (long)((double)k0 * scale) - 400;   // ~7 sigma margin
        long rs1 = (long)((double)k1 * scale) + 400;
        if (rs0 < 0) rs0 = 0;
        if (rs1 > (long)S - 1) rs1 = (long)S - 1;
        sh_rs0 = (unsigned)rs0;
        sh_rs1 = (unsigned)rs1;
    }
    __syncthreads();

    const unsigned rs0 = sh_rs0, rs1 = sh_rs1;
    unsigned cum = seg[tid];
    int lob = NBINS, hib = NBINS;
#pragma unroll
    for (int j = 0; j < 16; ++j) {
        cum += local[j];
        if (lob == NBINS && cum > rs0) lob = tid * 16 + j;
        if (hib == NBINS && cum > rs1) hib = tid * 16 + j;
    }
    if (lob < NBINS) atomicMin(&sh_lob, lob);
    if (hib < NBINS) atomicMin(&sh_hib, hib);
    __syncthreads();

    if (tid == 0) {
        int lo = (sh_lob < NBINS) ? sh_lob : NBINS - 1;
        int hi = (sh_hib < NBINS) ? sh_hib : NBINS - 1;
        unsigned lob_ = ((unsigned)lo) << 19;
        unsigned hib_ = ((unsigned)(hi + 1)) << 19;   // exclusive
        g_lo_bits[b] = lob_;
        g_hi_bits[b] = hib_;
        unsigned span = hib_ - lob_;
        unsigned sh = 7;
        while (span > ((unsigned)FINEBINS << sh)) ++sh;
        g_shift[b] = sh;
    }
}

// ---------------- K3: below-count + compaction + exact fine hist ------------
// One block = one contiguous 8192-element chunk of ONE batch; 4096 blocks.
// Candidates stashed per-thread (conflict-free smem), block scan, one global
// atomic per block. Fine histogram is EXACT over all candidates.
__global__ void __launch_bounds__(256) k3_compact(const float* __restrict__ s) {
    __shared__ unsigned sh_fine[FINEBINS];           // 16KB
    __shared__ unsigned sh_stash[STASH * 256];       // 16KB, [slot*256 + tid]
    __shared__ unsigned sh_wscan[8];
    __shared__ int sh_below[8];
    __shared__ unsigned sh_base;

    const int tid  = threadIdx.x;
    const int warp = tid >> 5;
    const int lane = tid & 31;
    const int b     = blockIdx.x >> 7;       // 128 blocks per batch
    const int chunk = blockIdx.x & 127;

    for (int i = tid; i < FINEBINS; i += 256) sh_fine[i] = 0u;
    __syncthreads();

    const unsigned lo = g_lo_bits[b];
    const unsigned hi = g_hi_bits[b];
    const unsigned fsh = g_shift[b];
    const float4* s4 = (const float4*)s + (size_t)b * (NPB / 4) + (size_t)chunk * 2048;

    int below = 0;
    unsigned cnt = 0;
#pragma unroll
    for (int it = 0; it < 8; ++it) {
        float4 v = s4[it * 256 + tid];
        unsigned bv[4];
        bv[0] = __float_as_uint(fabsf(v.x));
        bv[1] = __float_as_uint(fabsf(v.y));
        bv[2] = __float_as_uint(fabsf(v.z));
        bv[3] = __float_as_uint(fabsf(v.w));
#pragma unroll
        for (int j = 0; j < 4; ++j) {
            below += (bv[j] < lo);
            if (bv[j] >= lo && bv[j] < hi) {
                atomicAdd(&sh_fine[(bv[j] - lo) >> fsh], 1u);
                if (cnt < STASH) {
                    sh_stash[cnt * 256 + tid] = bv[j];
                } else {
                    // rare spill (P ~ 1e-6 per thread): direct global slot
                    unsigned slot = atomicAdd(&g_count[b][0], 1u);
                    if (slot < CAP) g_buf[b][slot] = bv[j];
                }
                cnt++;
            }
        }
    }

    // warp-reduce below; warp-scan stash counts
    int bl = below;
#pragma unroll
    for (int o = 16; o; o >>= 1) bl += __shfl_xor_sync(0xffffffffu, bl, o);
    if (lane == 0) sh_below[warp] = bl;

    unsigned sc = (cnt < STASH) ? cnt : STASH;
    unsigned x = sc;
#pragma unroll
    for (int o = 1; o < 32; o <<= 1) {
        unsigned y = __shfl_up_sync(0xffffffffu, x, o);
        if (lane >= o) x += y;
    }
    unsigned wex = x - sc;                     // exclusive within warp
    if (lane == 31) sh_wscan[warp] = x;        // warp total
    __syncthreads();

    if (tid == 0) {
        int tot = 0;
        for (int w = 0; w < 8; ++w) tot += sh_below[w];
        if (tot) atomicAdd(&g_below[b][0], (unsigned)tot);
        unsigned run = 0;
        for (int w = 0; w < 8; ++w) { unsigned v = sh_wscan[w]; sh_wscan[w] = run; run += v; }
        sh_base = atomicAdd(&g_count[b][0], run);
    }
    __syncthreads();

    const unsigned base = sh_base + sh_wscan[warp] + wex;
    for (unsigned j = 0; j < sc; ++j) {
        unsigned off = base + j;
        if (off < CAP) g_buf[b][off] = sh_stash[j * 256 + tid];
    }

    // flush exact fine hist
    for (int i = tid; i < FINEBINS; i += 256) {
        unsigned v = sh_fine[i];
        if (v) atomicAdd(&g_fine[b][i], v);
    }
}

// ---------------- K4: fine-hist scan + ONE pass exact select ----------------
// 32 blocks (one per batch) x 1024 threads.
__global__ void __launch_bounds__(1024) k4_select() {
    const int b = blockIdx.x;
    const int tid = threadIdx.x;
    const int lane = tid & 31;
    const int warp = tid >> 5;

    __shared__ unsigned sh_warp[32];
    __shared__ unsigned sh_tot;
    __shared__ int sh_bin0, sh_bin1;
    __shared__ unsigned sh_rr0, sh_rr1;
    __shared__ unsigned sh_n0, sh_n1;
    __shared__ float sh_v0, sh_v1;
    __shared__ unsigned sh_l0[LIST_CAP];
    __shared__ unsigned sh_l1[LIST_CAP];

    if (tid == 0) {
        sh_bin0 = -1; sh_bin1 = -1;
        sh_n0 = 0; sh_n1 = 0;
        sh_v0 = 0.f; sh_v1 = 0.f;
    }

    // load 4 fine bins per thread, block exclusive scan of thread sums
    unsigned f[4];
    unsigned ssum = 0;
#pragma unroll
    for (int j = 0; j < 4; ++j) { f[j] = g_fine[b][tid * 4 + j]; ssum += f[j]; }

    unsigned x = ssum;
#pragma unroll
    for (int o = 1; o < 32; o <<= 1) {
        unsigned y = __shfl_up_sync(0xffffffffu, x, o);
        if (lane >= o) x += y;
    }
    unsigned wex = x - ssum;
    if (lane == 31) sh_warp[warp] = x;
    __syncthreads();
    if (warp == 0) {
        unsigned v = sh_warp[lane];
        unsigned y = v;
#pragma unroll
        for (int o = 1; o < 32; o <<= 1) {
            unsigned z = __shfl_up_sync(0xffffffffu, y, o);
            if (lane >= o) y += z;
        }
        sh_warp[lane] = y - v;          // exclusive warp base
        if (lane == 31) sh_tot = y;     // total candidates (== m)
    }
    __syncthreads();

    const unsigned total = sh_tot;
    if (total == 0) { if (tid == 0) g_thresh[b] = 0.f; return; }

    const unsigned below = g_below[b][0];
    long r0l = (long)g_k0[b] - (long)below;
    long r1l = (long)g_k1[b] - (long)below;
    if (r0l < 0) r0l = 0;
    if (r1l < 0) r1l = 0;
    if (r0l >= (long)total) r0l = total - 1;
    if (r1l >= (long)total) r1l = total - 1;
    const unsigned r0 = (unsigned)r0l, r1 = (unsigned)r1l;

    // locate target fine bins + within-bin ranks
    unsigned cum = sh_warp[warp] + wex;
#pragma unroll
    for (int j = 0; j < 4; ++j) {
        unsigned c = f[j];
        if (c) {
            if (r0 >= cum && r0 < cum + c) { sh_bin0 = tid * 4 + j; sh_rr0 = r0 - cum; }
            if (r1 >= cum && r1 < cum + c) { sh_bin1 = tid * 4 + j; sh_rr1 = r1 - cum; }
        }
        cum += c;
    }
    __syncthreads();

    const int bin0 = sh_bin0, bin1 = sh_bin1;
    const unsigned lo = g_lo_bits[b];
    const unsigned fsh = g_shift[b];
    unsigned m = g_count[b][0];
    if (m > CAP) m = CAP;

    // ONE pass over candidates: collect only target-bin values
    for (unsigned i = tid; i < m; i += 1024) {
        unsigned v = __ldcg(&g_buf[b][i]);
        int key = (int)((v - lo) >> fsh);
        if (key == bin0) {
            unsigned p = atomicAdd(&sh_n0, 1u);
            if (p < LIST_CAP) sh_l0[p] = v;
        } else if (key == bin1) {
            unsigned p = atomicAdd(&sh_n1, 1u);
            if (p < LIST_CAP) sh_l1[p] = v;
        }
    }
    __syncthreads();

    // exact rank-by-count within the small lists
    unsigned n0 = sh_n0 < LIST_CAP ? sh_n0 : LIST_CAP;
    const unsigned rr0 = sh_rr0;
    for (unsigned t = tid; t < n0; t += 1024) {
        unsigned v = sh_l0[t];
        unsigned lt = 0, eq = 0;
        for (unsigned j = 0; j < n0; ++j) {
            unsigned w = sh_l0[j];
            lt += (w < v);
            eq += (w == v);
        }
        if (lt <= rr0 && rr0 < lt + eq) sh_v0 = __uint_as_float(v);
    }
    if (bin1 == bin0) {
        const unsigned rr1 = sh_rr1;
        for (unsigned t = tid; t < n0; t += 1024) {
            unsigned v = sh_l0[t];
            unsigned lt = 0, eq = 0;
            for (unsigned j = 0; j < n0; ++j) {
                unsigned w = sh_l0[j];
                lt += (w < v);
                eq += (w == v);
            }
            if (lt <= rr1 && rr1 < lt + eq) sh_v1 = __uint_as_float(v);
        }
    } else {
        unsigned n1 = sh_n1 < LIST_CAP ? sh_n1 : LIST_CAP;
        const unsigned rr1 = sh_rr1;
        for (unsigned t = tid; t < n1; t += 1024) {
            unsigned v = sh_l1[t];
            unsigned lt = 0, eq = 0;
            for (unsigned j = 0; j < n1; ++j) {
                unsigned w = sh_l1[j];
                lt += (w < v);
                eq += (w == v);
            }
            if (lt <= rr1 && rr1 < lt + eq) sh_v1 = __uint_as_float(v);
        }
    }
    __syncthreads();

    if (tid == 0) {
        float f0 = sh_v0, f1 = sh_v1;
        g_thresh[b] = f0 + (f1 - f0) * g_frac[b];
    }
}

// ---------------- K5: clip stream -------------------------------------------
__global__ void __launch_bounds__(256) k5_clip(const float* __restrict__ s,
                                               float* __restrict__ out)
{
    const float4* s4 = (const float4*)s;
    float4* o4 = (float4*)out;
    const unsigned total4 = (unsigned)BSZ * (NPB / 4);
    const unsigned stride = gridDim.x * blockDim.x;
    for (unsigned i = blockIdx.x * blockDim.x + threadIdx.x; i < total4; i += stride) {
        const int b = i >> 18;
        const float th = g_thresh[b];
        float4 v = __ldcs(s4 + i);
        v.x = fminf(fmaxf(v.x, -th), th);
        v.y = fminf(fmaxf(v.y, -th), th);
        v.z = fminf(fmaxf(v.z, -th), th);
        v.w = fminf(fmaxf(v.w, -th), th);
        __stcs(o4 + i, v);
    }
}

// ---------------- launch -----------------------------------------------------
extern "C" void kernel_launch(void* const* d_in, const int* in_sizes, int n_in,
                              void* d_out, int out_size)
{
    const float* s    = (const float*)d_in[0];
    const float* t    = (const float*)d_in[1];
    const float* risk = (const float*)d_in[2];
    float* out = (float*)d_out;

    k0_zero<<<512, 256>>>();
    k1_stats<<<1024, 256>>>(s, t, risk);
    k2_buckets<<<BSZ, 256>>>();
    k3_compact<<<4096, 256>>>(s);
    k4_select<<<BSZ, 1024>>>();
    k5_clip<<<8192, 256>>>(s, out);
}

// round 5
// speedup vs baseline: 1.7736x; 1.4144x over previous
#include <cuda_runtime.h>
#include <cstdint>

// Problem shape (fixed by the dataset)
#define BSZ 32
#define TLEN 4096
#define CDIM 256
#define NPB (TLEN * CDIM)        // 1048576 elements per batch
#define NBINS 4096               // coarse: (bits of fabs(x)) >> 19
#define FINEBINS 4096            // fine hist over candidate window (built in K4)
#define CAP 131072               // candidate buffer capacity per batch
#define PAD 64                   // 256B stride -> distinct L2 lines
#define STASH 16                 // per-thread candidate stash (spill path for more)
#define LIST_CAP 4096            // K4 per-bin collection capacity

// ---------------- device scratch (static, allocation-free) ----------------
__device__ float    g_distrust[BSZ][PAD];
__device__ unsigned g_hist[BSZ][NBINS];
__device__ unsigned g_count[BSZ][PAD];
__device__ unsigned g_below[BSZ][PAD];
__device__ unsigned g_lo_bits[BSZ];
__device__ unsigned g_span[BSZ];
__device__ unsigned g_shift[BSZ];
__device__ unsigned g_k0[BSZ];
__device__ unsigned g_k1[BSZ];
__device__ float    g_frac[BSZ];
__device__ float    g_thresh[BSZ];
__device__ unsigned g_buf[BSZ][CAP];

// ---------------- K0: zero scratch (graph replays need this) ----------------
__global__ void k0_zero() {
    unsigned i = blockIdx.x * blockDim.x + threadIdx.x;
    unsigned stride = gridDim.x * blockDim.x;
    unsigned n1 = BSZ * NBINS;
    unsigned* h = &g_hist[0][0];
    for (unsigned j = i; j < n1; j += stride) h[j] = 0u;
    if (i < BSZ) {
        g_distrust[i][0] = 0.f;
        g_count[i][0] = 0u;
        g_below[i][0] = 0u;
    }
}

// ---------------- K1: distrust stats + subsampled histogram ----------------
// Grid: 1024 blocks x 256 threads. Block handles 128 rows (one batch each).
__global__ void __launch_bounds__(256) k1_stats(
    const float* __restrict__ s, const float* __restrict__ t,
    const float* __restrict__ risk)
{
    __shared__ unsigned sh_hist[NBINS];
    __shared__ float sh_wsum[8];
    const int tid  = threadIdx.x;
    const int warp = tid >> 5;
    const int lane = tid & 31;

    for (int i = tid; i < NBINS; i += 256) sh_hist[i] = 0u;
    __syncthreads();

    const int row0 = blockIdx.x * 128;
    const int b = row0 / TLEN;
    const float rc = risk[b];

    float acc = 0.f;
#pragma unroll 4
    for (int it = 0; it < 16; ++it) {
        const int row = row0 + warp * 16 + it;
        const size_t base = (size_t)row * CDIM + lane * 8;
        float4 s0 = *(const float4*)(s + base);
        float4 s1 = *(const float4*)(s + base + 4);
        float4 t0 = __ldcs((const float4*)(t + base));
        float4 t1 = __ldcs((const float4*)(t + base + 4));

        // subsample: 8 of 256 elements per row -> 1/32 rate, 32768/batch
        if ((lane & 3) == 0) {
            unsigned bits = __float_as_uint(fabsf(s0.x));
            atomicAdd(&sh_hist[bits >> 19], 1u);
        }

        float d0 = s0.x - t0.x, d1 = s0.y - t0.y, d2 = s0.z - t0.z, d3 = s0.w - t0.w;
        float d4 = s1.x - t1.x, d5 = s1.y - t1.y, d6 = s1.z - t1.z, d7 = s1.w - t1.w;
        float r = d0*d0 + d1*d1 + d2*d2 + d3*d3 + d4*d4 + d5*d5 + d6*d6 + d7*d7;
#pragma unroll
        for (int o = 16; o; o >>= 1) r += __shfl_xor_sync(0xffffffffu, r, o);
        if (lane == 0) {
            float delta = r * (1.f / CDIM);
            float u = fminf(fmaxf(delta * 2.f, 0.f), 1.f);
            acc += fmaxf(u, rc * u);
        }
    }
    if (lane == 0) sh_wsum[warp] = acc;
    __syncthreads();
    if (tid == 0) {
        float ssum = 0.f;
        for (int w = 0; w < 8; ++w) ssum += sh_wsum[w];
        atomicAdd(&g_distrust[b][0], ssum);
    }
    for (int i = tid; i < NBINS; i += 256) {
        unsigned v = sh_hist[i];
        if (v) atomicAdd(&g_hist[b][i], v);
    }
}

// ---------------- K2: ranks + candidate window + fine shift -----------------
// 32 blocks (one per batch) x 256 threads.
__global__ void __launch_bounds__(256) k2_buckets() {
    const int b = blockIdx.x;
    const int tid = threadIdx.x;
    __shared__ unsigned seg[256];
    __shared__ int sh_lob, sh_hib;
    __shared__ unsigned sh_rs0, sh_rs1;

    if (tid == 0) { sh_lob = NBINS; sh_hib = NBINS; }

    unsigned local[16];
    unsigned ssum = 0;
#pragma unroll
    for (int j = 0; j < 16; ++j) {
        local[j] = g_hist[b][tid * 16 + j];
        ssum += local[j];
    }
    seg[tid] = ssum;
    __syncthreads();

    if (tid == 0) {
        unsigned run = 0;
        for (int i = 0; i < 256; ++i) { unsigned v = seg[i]; seg[i] = run; run += v; }

        float db = g_distrust[b][0] * (1.f / TLEN);
        float p = 0.99f - 0.09f * db;
        double pos = (double)p * (double)(NPB - 1);
        unsigned k0 = (unsigned)pos;
        if (k0 > NPB - 1) k0 = NPB - 1;
        double frac = pos - (double)k0;
        unsigned k1 = (k0 + 1 <= NPB - 1) ? k0 + 1 : NPB - 1;
        g_k0[b] = k0;
        g_k1[b] = k1;
        g_frac[b] = (float)frac;

        const unsigned S = TLEN * 8;                // samples per batch
        double scale = (double)S / (double)NPB;
        long rs0 = (long)((double)k0 * scale) - 400;   // ~7 sigma margin
        long rs1 = (long)((double)k1 * scale) + 400;
        if (rs0 < 0) rs0 = 0;
        if (rs1 > (long)S - 1) rs1 = (long)S - 1;
        sh_rs0 = (unsigned)rs0;
        sh_rs1 = (unsigned)rs1;
    }
    __syncthreads();

    const unsigned rs0 = sh_rs0, rs1 = sh_rs1;
    unsigned cum = seg[tid];
    int lob = NBINS, hib = NBINS;
#pragma unroll
    for (int j = 0; j < 16; ++j) {
        cum += local[j];
        if (lob == NBINS && cum > rs0) lob = tid * 16 + j;
        if (hib == NBINS && cum > rs1) hib = tid * 16 + j;
    }
    if (lob < NBINS) atomicMin(&sh_lob, lob);
    if (hib < NBINS) atomicMin(&sh_hib, hib);
    __syncthreads();

    if (tid == 0) {
        int lo = (sh_lob < NBINS) ? sh_lob : NBINS - 1;
        int hi = (sh_hib < NBINS) ? sh_hib : NBINS - 1;
        unsigned lob_ = ((unsigned)lo) << 19;
        unsigned hib_ = ((unsigned)(hi + 1)) << 19;   // exclusive
        unsigned span = hib_ - lob_;
        g_lo_bits[b] = lob_;
        g_span[b] = span;
        unsigned sh = 7;
        while (span > ((unsigned)FINEBINS << sh)) ++sh;
        g_shift[b] = sh;
    }
}

// ---------------- K3: below-count + compaction (lean streaming pass) --------
// One block = one contiguous 8192-element chunk of ONE batch; 4096 blocks.
// Per element: abs-bits, u = bv - lo; below += u>>31; candidate iff u < span.
// Candidates stashed per-thread (conflict-free smem), block scan, one global
// atomic per block.
__global__ void __launch_bounds__(256) k3_compact(const float* __restrict__ s) {
    __shared__ unsigned sh_stash[STASH * 256];       // 16KB, [slot*256 + tid]
    __shared__ unsigned sh_wscan[8];
    __shared__ unsigned sh_below[8];
    __shared__ unsigned sh_base;

    const int tid  = threadIdx.x;
    const int warp = tid >> 5;
    const int lane = tid & 31;
    const int b     = blockIdx.x >> 7;       // 128 blocks per batch
    const int chunk = blockIdx.x & 127;

    const unsigned lo   = g_lo_bits[b];
    const unsigned span = g_span[b];
    const float4* s4 = (const float4*)s + (size_t)b * (NPB / 4) + (size_t)chunk * 2048;

    unsigned below = 0;
    unsigned cnt = 0;
#pragma unroll
    for (int it = 0; it < 8; ++it) {
        float4 v = s4[it * 256 + tid];
        unsigned u0 = (__float_as_uint(v.x) & 0x7fffffffu) - lo;
        unsigned u1 = (__float_as_uint(v.y) & 0x7fffffffu) - lo;
        unsigned u2 = (__float_as_uint(v.z) & 0x7fffffffu) - lo;
        unsigned u3 = (__float_as_uint(v.w) & 0x7fffffffu) - lo;
        below += (u0 >> 31) + (u1 >> 31) + (u2 >> 31) + (u3 >> 31);
        if (u0 < span) { if (cnt < STASH) sh_stash[cnt * 256 + tid] = u0 + lo; else { unsigned sl = atomicAdd(&g_count[b][0], 1u); if (sl < CAP) g_buf[b][sl] = u0 + lo; } cnt++; }
        if (u1 < span) { if (cnt < STASH) sh_stash[cnt * 256 + tid] = u1 + lo; else { unsigned sl = atomicAdd(&g_count[b][0], 1u); if (sl < CAP) g_buf[b][sl] = u1 + lo; } cnt++; }
        if (u2 < span) { if (cnt < STASH) sh_stash[cnt * 256 + tid] = u2 + lo; else { unsigned sl = atomicAdd(&g_count[b][0], 1u); if (sl < CAP) g_buf[b][sl] = u2 + lo; } cnt++; }
        if (u3 < span) { if (cnt < STASH) sh_stash[cnt * 256 + tid] = u3 + lo; else { unsigned sl = atomicAdd(&g_count[b][0], 1u); if (sl < CAP) g_buf[b][sl] = u3 + lo; } cnt++; }
    }

    // warp-reduce below; warp-scan stash counts
    unsigned bl = below;
#pragma unroll
    for (int o = 16; o; o >>= 1) bl += __shfl_xor_sync(0xffffffffu, bl, o);
    if (lane == 0) sh_below[warp] = bl;

    unsigned sc = (cnt < STASH) ? cnt : STASH;
    unsigned x = sc;
#pragma unroll
    for (int o = 1; o < 32; o <<= 1) {
        unsigned y = __shfl_up_sync(0xffffffffu, x, o);
        if (lane >= o) x += y;
    }
    unsigned wex = x - sc;                     // exclusive within warp
    if (lane == 31) sh_wscan[warp] = x;        // warp total
    __syncthreads();

    if (tid == 0) {
        unsigned tot = 0;
        for (int w = 0; w < 8; ++w) tot += sh_below[w];
        if (tot) atomicAdd(&g_below[b][0], tot);
        unsigned run = 0;
        for (int w = 0; w < 8; ++w) { unsigned v = sh_wscan[w]; sh_wscan[w] = run; run += v; }
        sh_base = atomicAdd(&g_count[b][0], run);
    }
    __syncthreads();

    const unsigned base = sh_base + sh_wscan[warp] + wex;
    for (unsigned j = 0; j < sc; ++j) {
        unsigned off = base + j;
        if (off < CAP) g_buf[b][off] = sh_stash[j * 256 + tid];
    }
}

// ---------------- K4: hist build + scan + ONE pass exact select -------------
// 32 blocks (one per batch) x 1024 threads. Candidate buffer (~160KB) is
// L2-resident; two passes over it are cheap.
__global__ void __launch_bounds__(1024) k4_select() {
    const int b = blockIdx.x;
    const int tid = threadIdx.x;
    const int lane = tid & 31;
    const int warp = tid >> 5;

    __shared__ unsigned sh_fine[FINEBINS];          // 16KB
    __shared__ unsigned sh_warp[32];
    __shared__ unsigned sh_tot;
    __shared__ int sh_bin0, sh_bin1;
    __shared__ unsigned sh_rr0, sh_rr1;
    __shared__ unsigned sh_n0, sh_n1;
    __shared__ float sh_v0, sh_v1;
    __shared__ unsigned sh_l0[LIST_CAP];
    __shared__ unsigned sh_l1[LIST_CAP];

    if (tid == 0) {
        sh_bin0 = -1; sh_bin1 = -1;
        sh_n0 = 0; sh_n1 = 0;
        sh_v0 = 0.f; sh_v1 = 0.f;
    }
    for (int i = tid; i < FINEBINS; i += 1024) sh_fine[i] = 0u;
    __syncthreads();

    const unsigned lo = g_lo_bits[b];
    const unsigned fsh = g_shift[b];
    unsigned m = g_count[b][0];
    if (m > CAP) m = CAP;

    // pass 1: exact fine hist from candidate buffer
    for (unsigned i = tid; i < m; i += 1024)
        atomicAdd(&sh_fine[(__ldcg(&g_buf[b][i]) - lo) >> fsh], 1u);
    __syncthreads();

    // block exclusive scan of 4096 bins (4/thread)
    unsigned f[4];
    unsigned ssum = 0;
#pragma unroll
    for (int j = 0; j < 4; ++j) { f[j] = sh_fine[tid * 4 + j]; ssum += f[j]; }

    unsigned x = ssum;
#pragma unroll
    for (int o = 1; o < 32; o <<= 1) {
        unsigned y = __shfl_up_sync(0xffffffffu, x, o);
        if (lane >= o) x += y;
    }
    unsigned wex = x - ssum;
    if (lane == 31) sh_warp[warp] = x;
    __syncthreads();
    if (warp == 0) {
        unsigned v = sh_warp[lane];
        unsigned y = v;
#pragma unroll
        for (int o = 1; o < 32; o <<= 1) {
            unsigned z = __shfl_up_sync(0xffffffffu, y, o);
            if (lane >= o) y += z;
        }
        sh_warp[lane] = y - v;          // exclusive warp base
        if (lane == 31) sh_tot = y;     // total candidates
    }
    __syncthreads();

    const unsigned total = sh_tot;
    if (total == 0) { if (tid == 0) g_thresh[b] = 0.f; return; }

    const unsigned below = g_below[b][0];
    long r0l = (long)g_k0[b] - (long)below;
    long r1l = (long)g_k1[b] - (long)below;
    if (r0l < 0) r0l = 0;
    if (r1l < 0) r1l = 0;
    if (r0l >= (long)total) r0l = total - 1;
    if (r1l >= (long)total) r1l = total - 1;
    const unsigned r0 = (unsigned)r0l, r1 = (unsigned)r1l;

    // locate target fine bins + within-bin ranks
    unsigned cum = sh_warp[warp] + wex;
#pragma unroll
    for (int j = 0; j < 4; ++j) {
        unsigned c = f[j];
        if (c) {
            if (r0 >= cum && r0 < cum + c) { sh_bin0 = tid * 4 + j; sh_rr0 = r0 - cum; }
            if (r1 >= cum && r1 < cum + c) { sh_bin1 = tid * 4 + j; sh_rr1 = r1 - cum; }
        }
        cum += c;
    }
    __syncthreads();

    const int bin0 = sh_bin0, bin1 = sh_bin1;

    // pass 2: collect only target-bin values
    for (unsigned i = tid; i < m; i += 1024) {
        unsigned v = __ldcg(&g_buf[b][i]);
        int key = (int)((v - lo) >> fsh);
        if (key == bin0) {
            unsigned p = atomicAdd(&sh_n0, 1u);
            if (p < LIST_CAP) sh_l0[p] = v;
        } else if (key == bin1) {
            unsigned p = atomicAdd(&sh_n1, 1u);
            if (p < LIST_CAP) sh_l1[p] = v;
        }
    }
    __syncthreads();

    // exact rank-by-count within the small lists
    unsigned n0 = sh_n0 < LIST_CAP ? sh_n0 : LIST_CAP;
    const unsigned rr0 = sh_rr0;
    for (unsigned t = tid; t < n0; t += 1024) {
        unsigned v = sh_l0[t];
        unsigned lt = 0, eq = 0;
        for (unsigned j = 0; j < n0; ++j) {
            unsigned w = sh_l0[j];
            lt += (w < v);
            eq += (w == v);
        }
        if (lt <= rr0 && rr0 < lt + eq) sh_v0 = __uint_as_float(v);
    }
    if (bin1 == bin0) {
        const unsigned rr1 = sh_rr1;
        for (unsigned t = tid; t < n0; t += 1024) {
            unsigned v = sh_l0[t];
            unsigned lt = 0, eq = 0;
            for (unsigned j = 0; j < n0; ++j) {
                unsigned w = sh_l0[j];
                lt += (w < v);
                eq += (w == v);
            }
            if (lt <= rr1 && rr1 < lt + eq) sh_v1 = __uint_as_float(v);
        }
    } else {
        unsigned n1 = sh_n1 < LIST_CAP ? sh_n1 : LIST_CAP;
        const unsigned rr1 = sh_rr1;
        for (unsigned t = tid; t < n1; t += 1024) {
            unsigned v = sh_l1[t];
            unsigned lt = 0, eq = 0;
            for (unsigned j = 0; j < n1; ++j) {
                unsigned w = sh_l1[j];
                lt += (w < v);
                eq += (w == v);
            }
            if (lt <= rr1 && rr1 < lt + eq) sh_v1 = __uint_as_float(v);
        }
    }
    __syncthreads();

    if (tid == 0) {
        float f0 = sh_v0, f1 = sh_v1;
        g_thresh[b] = f0 + (f1 - f0) * g_frac[b];
    }
}

// ---------------- K5: clip stream -------------------------------------------
__global__ void __launch_bounds__(256) k5_clip(const float* __restrict__ s,
                                               float* __restrict__ out)
{
    const float4* s4 = (const float4*)s;
    float4* o4 = (float4*)out;
    const unsigned total4 = (unsigned)BSZ * (NPB / 4);
    const unsigned stride = gridDim.x * blockDim.x;
    for (unsigned i = blockIdx.x * blockDim.x + threadIdx.x; i < total4; i += stride) {
        const int b = i >> 18;
        const float th = g_thresh[b];
        float4 v = __ldcs(s4 + i);
        v.x = fminf(fmaxf(v.x, -th), th);
        v.y = fminf(fmaxf(v.y, -th), th);
        v.z = fminf(fmaxf(v.z, -th), th);
        v.w = fminf(fmaxf(v.w, -th), th);
        __stcs(o4 + i, v);
    }
}

// ---------------- launch -----------------------------------------------------
extern "C" void kernel_launch(void* const* d_in, const int* in_sizes, int n_in,
                              void* d_out, int out_size)
{
    const float* s    = (const float*)d_in[0];
    const float* t    = (const float*)d_in[1];
    const float* risk = (const float*)d_in[2];
    float* out = (float*)d_out;

    k0_zero<<<512, 256>>>();
    k1_stats<<<1024, 256>>>(s, t, risk);
    k2_buckets<<<BSZ, 256>>>();
    k3_compact<<<4096, 256>>>(s);
    k4_select<<<BSZ, 1024>>>();
    k5_clip<<<8192, 256>>>(s, out);
}